// round 13
// baseline (speedup 1.0000x reference)
#include <cuda_runtime.h>

// out[i,c] = 8! * sum_j ( relu(x @ W1 + b1) @ W2 + b2 )[j,c]   (row-constant)
//
// R12 == R9 (converged plateau; A/A confirmation of the launch-overhead
// floor). Permutation-symmetry collapse: every row j lands in every output
// position exactly (N-1)! times, so the N!-permutation gather+sum reduces
// to one tiny MLP + column sum. perms (13MB) is never read.
//
// Single CTA, 512 threads:
//  - x transposed into smem warp-locally (no CTA barrier before compute)
//  - W1 read once, rank-1-update form, packed f32x2 FMAs (5 accs = 9 rows)
//  - psum packed STS.64 conflict-free; producers bar.arrive+exit
//  - fixed-order packed-add reduction trees (bitwise deterministic)
//  - warp-per-output-column tail with xor-butterfly

static constexpr int N = 9;
static constexpr int D = 512;
static constexpr int H = 32;
static constexpr int THREADS = 512;
static constexpr int WARPS = 16;
static constexpr int DPW = D / WARPS;     // 32 d-values per warp
static constexpr int XPAD = 12;           // floats per xT row (48B)
static constexpr int PAIRS = 5;           // (0,1)(2,3)(4,5)(6,7)(8,pad)
static constexpr float FACT8 = 40320.0f;  // (N-1)!

typedef unsigned long long u64;

__global__ void __launch_bounds__(THREADS, 1)
sym_kernel(const float* __restrict__ x,
           const float* __restrict__ W1,
           const float* __restrict__ b1,
           const float* __restrict__ W2,
           const float* __restrict__ b2,
           float* __restrict__ out) {
    __shared__ __align__(16) float xT[D * XPAD];          // xT[d][r]
    __shared__ __align__(16) u64 psum[WARPS * PAIRS * H]; // [w][p*H + k]
    __shared__ __align__(16) u64 hp[H * PAIRS];           // [k][p] packed relu'd

    const int t = threadIdx.x;
    const int w = t >> 5;   // warp 0..15
    const int k = t & 31;   // lane

    // ---- per-warp prefetch (no CTA barrier before mainloop) ----
#pragma unroll
    for (int r = 0; r < N; r++)
        xT[t * XPAD + r] = x[r * D + t];
    xT[t * XPAD + 9] = 0.0f;   // pad slot read by the packed row-8 accumulator

    // W1 chunk -> packed (wv,wv) registers (packing in LDG shadow)
    u64 wpack[DPW];
    const float* W1p = W1 + (w * DPW) * H + k;
#pragma unroll
    for (int i = 0; i < DPW; i++) {
        unsigned wu = __float_as_uint(W1p[i * H]);
        asm("mov.b64 %0, {%1, %1};" : "=l"(wpack[i]) : "r"(wu));
    }

    // phase operands
    u64 b1p = 0;                      // (b1[k], b1[k]) for reduce warps
    if (w < PAIRS) {
        unsigned bu = __float_as_uint(b1[k]);
        asm("mov.b64 %0, {%1, %1};" : "=l"(b1p) : "r"(bu));
    }
    float w2c = 0.f, b2c = 0.f;
    if (w < 4) {                      // tail: warp c owns output column c
        w2c = W2[k * 4 + w];
        b2c = b2[w];
    }
    __syncwarp();   // xT slice is produced/consumed by this warp only

    // ---- rank-1-update partial dots: 5 packed f32x2 accumulators ----
    u64 a01 = 0, a23 = 0, a45 = 0, a67 = 0, a89 = 0;
    const float* xrow = xT + (w * DPW) * XPAD;
#pragma unroll
    for (int i = 0; i < DPW; i++) {
        const float* xp = xrow + i * XPAD;            // 48B-aligned
        ulonglong2 p0 = *(const ulonglong2*)(xp);     // rows 0..3 (bcast)
        u64 p2 = *(const u64*)(xp + 4);               // rows 4,5
        u64 p3 = *(const u64*)(xp + 6);               // rows 6,7
        u64 p4 = *(const u64*)(xp + 8);               // rows 8,pad
        u64 ww = wpack[i];
        asm("fma.rn.f32x2 %0, %1, %2, %0;" : "+l"(a01) : "l"(p0.x), "l"(ww));
        asm("fma.rn.f32x2 %0, %1, %2, %0;" : "+l"(a23) : "l"(p0.y), "l"(ww));
        asm("fma.rn.f32x2 %0, %1, %2, %0;" : "+l"(a45) : "l"(p2),   "l"(ww));
        asm("fma.rn.f32x2 %0, %1, %2, %0;" : "+l"(a67) : "l"(p3),   "l"(ww));
        asm("fma.rn.f32x2 %0, %1, %2, %0;" : "+l"(a89) : "l"(p4),   "l"(ww));
    }
    {   // packed stores, lane stride 1 (conflict-free STS.64)
        u64* pp = psum + w * (PAIRS * H) + k;
        pp[0 * H] = a01;
        pp[1 * H] = a23;
        pp[2 * H] = a45;
        pp[3 * H] = a67;
        pp[4 * H] = a89;
    }

    // producers signal and exit; consumers wait
    if (w >= PAIRS) {
        asm volatile("bar.arrive 0, %0;" :: "r"(THREADS) : "memory");
        return;
    }
    asm volatile("bar.sync 0, %0;" :: "r"(THREADS) : "memory");

    // ---- reduce 16 warp partials for pair w, lane k (fixed tree) ----
    {
        u64 q[WARPS];
#pragma unroll
        for (int j = 0; j < WARPS; j++)
            q[j] = psum[j * (PAIRS * H) + w * H + k];   // LDS.64, CF
#pragma unroll
        for (int st = 1; st < WARPS; st <<= 1)
#pragma unroll
            for (int j = 0; j < WARPS; j += 2 * st)
                asm("add.rn.f32x2 %0, %0, %1;" : "+l"(q[j]) : "l"(q[j + st]));
        // packed bias, relu both halves, store packed
        asm("add.rn.f32x2 %0, %0, %1;" : "+l"(q[0]) : "l"(b1p));
        unsigned lo, hi;
        asm("mov.b64 {%0, %1}, %2;" : "=r"(lo), "=r"(hi) : "l"(q[0]));
        float hl = fmaxf(__uint_as_float(lo), 0.0f);
        float hh = fmaxf(__uint_as_float(hi), 0.0f);
        u64 hq;
        asm("mov.b64 %0, {%1, %2};" : "=l"(hq)
            : "r"(__float_as_uint(hl)), "r"(__float_as_uint(hh)));
        hp[k * PAIRS + w] = hq;      // lane stride 5 u64 -> <=2-way
    }
    asm volatile("bar.sync 1, %0;" :: "r"(PAIRS * H) : "memory");  // warps 0..4
    if (w == 4) return;

    // ---- tail: warp c computes output column c ----
    {
        const u64* hk = hp + k * PAIRS;
        u64 s01 = hk[0], s23 = hk[1], s45 = hk[2], s67 = hk[3], s8p = hk[4];
        asm("add.rn.f32x2 %0, %0, %1;" : "+l"(s01) : "l"(s23));
        asm("add.rn.f32x2 %0, %0, %1;" : "+l"(s45) : "l"(s67));
        asm("add.rn.f32x2 %0, %0, %1;" : "+l"(s01) : "l"(s45));
        unsigned lo, hi, l8, h8;
        asm("mov.b64 {%0, %1}, %2;" : "=r"(lo), "=r"(hi) : "l"(s01));
        asm("mov.b64 {%0, %1}, %2;" : "=r"(l8), "=r"(h8) : "l"(s8p));
        // row-8 pair's hi half is relu(b1) garbage from the pad: exclude it
        float s = (__uint_as_float(lo) + __uint_as_float(hi)) + __uint_as_float(l8);

        float v = s * w2c;
#pragma unroll
        for (int off = 16; off; off >>= 1)   // fixed xor tree
            v += __shfl_xor_sync(0xffffffffu, v, off);

        float val = FACT8 * fmaf((float)N, b2c, v);
        if (k < N) out[k * 4 + w] = val;     // out[r][c], r = lane
    }
}

extern "C" void kernel_launch(void* const* d_in, const int* in_sizes, int n_in,
                              void* d_out, int out_size) {
    // metadata order: x[9,512], W1[512,32], b1[32], W2[32,4], b2[4], perms (unused)
    const float* x  = (const float*)d_in[0];
    const float* W1 = (const float*)d_in[1];
    const float* b1 = (const float*)d_in[2];
    const float* W2 = (const float*)d_in[3];
    const float* b2 = (const float*)d_in[4];
    float* out = (float*)d_out;

    sym_kernel<<<1, THREADS>>>(x, W1, b1, W2, b2, out);
}

// round 16
// speedup vs baseline: 1.0435x; 1.0435x over previous
#include <cuda_runtime.h>

// out[i,c] = 8! * sum_j ( relu(x @ W1 + b1) @ W2 + b2 )[j,c]   (row-constant)
//
// R14 vs R12: single-warp tail. After psum, warps 1..15 bar.arrive+exit;
// warp 0 bar.sync and finishes everything (pair reductions, bias/relu,
// 4 interleaved xor-butterflies, 9x STG.128). Removes the second barrier
// and the hp smem round trip from the critical path.

static constexpr int N = 9;
static constexpr int D = 512;
static constexpr int H = 32;
static constexpr int THREADS = 512;
static constexpr int WARPS = 16;
static constexpr int DPW = D / WARPS;     // 32 d-values per warp
static constexpr int XPAD = 12;           // floats per xT row (48B)
static constexpr int PAIRS = 5;           // (0,1)(2,3)(4,5)(6,7)(8,pad)
static constexpr float FACT8 = 40320.0f;  // (N-1)!

typedef unsigned long long u64;

__global__ void __launch_bounds__(THREADS, 1)
sym_kernel(const float* __restrict__ x,
           const float* __restrict__ W1,
           const float* __restrict__ b1,
           const float* __restrict__ W2,
           const float* __restrict__ b2,
           float* __restrict__ out) {
    __shared__ __align__(16) float xT[D * XPAD];          // xT[d][r]
    __shared__ __align__(16) u64 psum[WARPS * PAIRS * H]; // [w][p*H + k]

    const int t = threadIdx.x;
    const int w = t >> 5;   // warp 0..15
    const int k = t & 31;   // lane

    // ---- per-warp prefetch (no CTA barrier before mainloop) ----
#pragma unroll
    for (int r = 0; r < N; r++)
        xT[t * XPAD + r] = x[r * D + t];
    xT[t * XPAD + 9] = 0.0f;   // pad slot read by the packed row-8 accumulator

    // W1 chunk -> packed (wv,wv) registers (packing in LDG shadow)
    u64 wpack[DPW];
    const float* W1p = W1 + (w * DPW) * H + k;
#pragma unroll
    for (int i = 0; i < DPW; i++) {
        unsigned wu = __float_as_uint(W1p[i * H]);
        asm("mov.b64 %0, {%1, %1};" : "=l"(wpack[i]) : "r"(wu));
    }

    // tail operands: warp 0 only
    u64 b1p = 0;
    float4 w2v = make_float4(0.f, 0.f, 0.f, 0.f);
    float4 b2v = make_float4(0.f, 0.f, 0.f, 0.f);
    if (w == 0) {
        unsigned bu = __float_as_uint(b1[k]);
        asm("mov.b64 %0, {%1, %1};" : "=l"(b1p) : "r"(bu));
        w2v = *(const float4*)(W2 + k * 4);   // W2[k][0..3]
        b2v = *(const float4*)(b2);           // broadcast
    }
    __syncwarp();   // xT slice is produced/consumed by this warp only

    // ---- rank-1-update partial dots: 5 packed f32x2 accumulators ----
    u64 a01 = 0, a23 = 0, a45 = 0, a67 = 0, a89 = 0;
    const float* xrow = xT + (w * DPW) * XPAD;
#pragma unroll
    for (int i = 0; i < DPW; i++) {
        const float* xp = xrow + i * XPAD;            // 48B-aligned
        ulonglong2 p0 = *(const ulonglong2*)(xp);     // rows 0..3 (bcast)
        ulonglong2 p1 = *(const ulonglong2*)(xp + 4); // rows 4..7
        u64 p4 = *(const u64*)(xp + 8);               // rows 8,pad
        u64 ww = wpack[i];
        asm("fma.rn.f32x2 %0, %1, %2, %0;" : "+l"(a01) : "l"(p0.x), "l"(ww));
        asm("fma.rn.f32x2 %0, %1, %2, %0;" : "+l"(a23) : "l"(p0.y), "l"(ww));
        asm("fma.rn.f32x2 %0, %1, %2, %0;" : "+l"(a45) : "l"(p1.x), "l"(ww));
        asm("fma.rn.f32x2 %0, %1, %2, %0;" : "+l"(a67) : "l"(p1.y), "l"(ww));
        asm("fma.rn.f32x2 %0, %1, %2, %0;" : "+l"(a89) : "l"(p4),   "l"(ww));
    }
    {   // packed stores, lane stride 1 (conflict-free STS.64)
        u64* pp = psum + w * (PAIRS * H) + k;
        pp[0 * H] = a01;
        pp[1 * H] = a23;
        pp[2 * H] = a45;
        pp[3 * H] = a67;
        pp[4 * H] = a89;
    }

    // producers signal and exit; warp 0 finishes alone
    if (w != 0) {
        asm volatile("bar.arrive 0, %0;" :: "r"(THREADS) : "memory");
        return;
    }
    asm volatile("bar.sync 0, %0;" :: "r"(THREADS) : "memory");

    // ---- warp 0: reduce all 5 pairs over 16 producer warps ----
    u64 hq[PAIRS];   // relu'd packed pairs
#pragma unroll
    for (int p = 0; p < PAIRS; p++) {
        u64 q[WARPS];
#pragma unroll
        for (int j = 0; j < WARPS; j++)
            q[j] = psum[j * (PAIRS * H) + p * H + k];   // LDS.64, CF
#pragma unroll
        for (int st = 1; st < WARPS; st <<= 1)          // fixed tree
#pragma unroll
            for (int j = 0; j < WARPS; j += 2 * st)
                asm("add.rn.f32x2 %0, %0, %1;" : "+l"(q[j]) : "l"(q[j + st]));
        asm("add.rn.f32x2 %0, %0, %1;" : "+l"(q[0]) : "l"(b1p));
        unsigned lo, hi;
        asm("mov.b64 {%0, %1}, %2;" : "=r"(lo), "=r"(hi) : "l"(q[0]));
        float hl = fmaxf(__uint_as_float(lo), 0.0f);
        float hh = fmaxf(__uint_as_float(hi), 0.0f);
        asm("mov.b64 %0, {%1, %2};" : "=l"(hq[p])
            : "r"(__float_as_uint(hl)), "r"(__float_as_uint(hh)));
    }

    // ---- s_k = sum_r relu(z)[r][k]  (same grouping as R9/R12 tail) ----
    float s;
    {
        u64 s01 = hq[0], s23 = hq[1], s45 = hq[2], s67 = hq[3], s8p = hq[4];
        asm("add.rn.f32x2 %0, %0, %1;" : "+l"(s01) : "l"(s23));
        asm("add.rn.f32x2 %0, %0, %1;" : "+l"(s45) : "l"(s67));
        asm("add.rn.f32x2 %0, %0, %1;" : "+l"(s01) : "l"(s45));
        unsigned lo, hi, l8, h8;
        asm("mov.b64 {%0, %1}, %2;" : "=r"(lo), "=r"(hi) : "l"(s01));
        asm("mov.b64 {%0, %1}, %2;" : "=r"(l8), "=r"(h8) : "l"(s8p));
        // row-8 pair's hi half is relu(b1) garbage from the pad: exclude it
        s = (__uint_as_float(lo) + __uint_as_float(hi)) + __uint_as_float(l8);
    }

    // ---- 4 interleaved xor-butterflies: v_c = sum_k s_k * W2[k][c] ----
    float v0 = s * w2v.x, v1 = s * w2v.y, v2 = s * w2v.z, v3 = s * w2v.w;
#pragma unroll
    for (int off = 16; off; off >>= 1) {   // fixed tree; 4 chains overlap
        v0 += __shfl_xor_sync(0xffffffffu, v0, off);
        v1 += __shfl_xor_sync(0xffffffffu, v1, off);
        v2 += __shfl_xor_sync(0xffffffffu, v2, off);
        v3 += __shfl_xor_sync(0xffffffffu, v3, off);
    }

    // ---- output: row-constant, 9 lanes write one float4 row each ----
    float4 val;
    val.x = FACT8 * fmaf((float)N, b2v.x, v0);
    val.y = FACT8 * fmaf((float)N, b2v.y, v1);
    val.z = FACT8 * fmaf((float)N, b2v.z, v2);
    val.w = FACT8 * fmaf((float)N, b2v.w, v3);
    if (k < N)
        *(float4*)(out + k * 4) = val;     // STG.128, out[r][0..3]
}

extern "C" void kernel_launch(void* const* d_in, const int* in_sizes, int n_in,
                              void* d_out, int out_size) {
    // metadata order: x[9,512], W1[512,32], b1[32], W2[32,4], b2[4], perms (unused)
    const float* x  = (const float*)d_in[0];
    const float* W1 = (const float*)d_in[1];
    const float* b1 = (const float*)d_in[2];
    const float* W2 = (const float*)d_in[3];
    const float* b2 = (const float*)d_in[4];
    float* out = (float*)d_out;

    sym_kernel<<<1, THREADS>>>(x, W1, b1, W2, b2, out);
}